// round 15
// baseline (speedup 1.0000x reference)
#include <cuda_runtime.h>
#include <cuda_bf16.h>
#include <cstdint>

#define D 128
#define MAXN 40000

// ------------------------- device scratch (no allocs) -----------------------
__device__ __align__(16) float g_AB[(size_t)MAXN * 256]; // [N][256]: A=nf@W1^T | B'=nf@W2^T+b_e
__device__ __align__(16) float g_agg[(size_t)MAXN * D];
__device__ __align__(16) float g_deg[MAXN];
// Fragment-packed weights, COLUMN-PERMUTED so each thread's acc covers 4
// consecutive logical columns per tile-pair (enables v4 epilogue ops).
__device__ __align__(16) uint4 g_pk[5 * 2 * 2048];

// ------------------------- smem layout --------------------------------------
#define ROWB 272                  // 136 bf16/row: 4-bank shift/row, LDSM conflict-free
#define A_LO_OFF 17408            // 64*272
#define SMEM_TILE 34816

__device__ __forceinline__ uint32_t smem_u32(const void* p) {
    uint32_t a;
    asm("{ .reg .u64 t; cvta.to.shared.u64 t, %1; cvt.u32.u64 %0, t; }" : "=r"(a) : "l"(p));
    return a;
}

#define LDM4(r, addr) \
    asm volatile("ldmatrix.sync.aligned.m8n8.x4.shared.b16 {%0,%1,%2,%3}, [%4];" \
        : "=r"((r)[0]), "=r"((r)[1]), "=r"((r)[2]), "=r"((r)[3]) : "r"(addr))

__device__ __forceinline__ void mma16816(float* c, const uint32_t* a, uint32_t b0, uint32_t b1) {
    asm volatile("mma.sync.aligned.m16n8k16.row.col.f32.bf16.bf16.f32 "
        "{%0,%1,%2,%3}, {%4,%5,%6,%7}, {%8,%9}, {%0,%1,%2,%3};"
        : "+f"(c[0]), "+f"(c[1]), "+f"(c[2]), "+f"(c[3])
        : "r"(a[0]), "r"(a[1]), "r"(a[2]), "r"(a[3]), "r"(b0), "r"(b1));
}

// no "memory" clobber: lets the compiler batch independent gathers around reds
__device__ __forceinline__ void red_v4(float* p, float4 v) {
    asm volatile("red.global.add.v4.f32 [%0], {%1,%2,%3,%4};"
                 :: "l"(p), "f"(v.x), "f"(v.y), "f"(v.z), "f"(v.w));
}

// NOT volatile: pure load, no side effects. This allows ptxas to hoist the
// epilogue gathers into the MMA shadow (they depend only on preloaded idx).
__device__ __forceinline__ float4 ldcg4(const float* p) {
    float4 v;
    asm("ld.global.cg.v4.f32 {%0,%1,%2,%3}, [%4];"
        : "=f"(v.x), "=f"(v.y), "=f"(v.z), "=f"(v.w) : "l"(p));
    return v;
}

__device__ __forceinline__ void split2(float x, float y, uint32_t& h, uint32_t& l) {
    __nv_bfloat162 hh = __floats2bfloat162_rn(x, y);
    __nv_bfloat162 ll = __floats2bfloat162_rn(x - __bfloat162float(hh.x),
                                              y - __bfloat162float(hh.y));
    h = *reinterpret_cast<uint32_t*>(&hh);
    l = *reinterpret_cast<uint32_t*>(&ll);
}

__device__ __forceinline__ void cvt_store(char* ph, float4 f0, float4 f1, int jj, float s) {
    f0.x *= s; f0.y *= s; f0.z *= s; f0.w *= s;
    f1.x *= s; f1.y *= s; f1.z *= s; f1.w *= s;
    uint4 H, L;
    split2(f0.x, f0.y, H.x, L.x);
    split2(f0.z, f0.w, H.y, L.y);
    split2(f1.x, f1.y, H.z, L.z);
    split2(f1.z, f1.w, H.w, L.w);
    *reinterpret_cast<uint4*>(ph + jj * 16) = H;
    *reinterpret_cast<uint4*>(ph + A_LO_OFF + jj * 16) = L;
}

// ---- 8-mma block helper -----------------------------------------------------
__device__ __forceinline__ void mma8(float acc[2][4][4], const uint32_t* a0,
                                     const uint32_t* a1, uint4 U0, uint4 U1) {
    mma16816(acc[0][0], a0, U0.x, U0.y);
    mma16816(acc[0][1], a0, U0.z, U0.w);
    mma16816(acc[0][2], a0, U1.x, U1.y);
    mma16816(acc[0][3], a0, U1.z, U1.w);
    mma16816(acc[1][0], a1, U0.x, U0.y);
    mma16816(acc[1][1], a1, U0.z, U0.w);
    mma16816(acc[1][2], a1, U1.x, U1.y);
    mma16816(acc[1][3], a1, U1.z, U1.w);
}

// 3-pass 64x128x128 MMA; B hi+lo via __ldg (L1), A via LDSM, a_hi reused
__device__ __forceinline__ void run_mma(uint32_t sa, int block, int warpm, int warpn,
                                        int lane, float acc[2][4][4]) {
    uint32_t arow = sa + (warpm * 32 + (lane & 15)) * ROWB + (lane >> 4) * 16;
    const uint4* __restrict__ Bb = g_pk + (size_t)block * 2 * 2048;
    int boff = warpn * 64 + lane;
    #pragma unroll
    for (int ks = 0; ks < 8; ++ks) {
        uint32_t a0[4], a1[4], c0[4], c1[4];
        uint4 U0 = __ldg(Bb + ks * 256 + boff);
        uint4 U1 = __ldg(Bb + ks * 256 + boff + 32);
        uint4 V0 = __ldg(Bb + 2048 + ks * 256 + boff);
        uint4 V1 = __ldg(Bb + 2048 + ks * 256 + boff + 32);
        LDM4(a0, arow + ks * 32);
        LDM4(a1, arow + 16 * ROWB + ks * 32);
        mma8(acc, a0, a1, U0, U1);                       // hi x hi
        mma8(acc, a0, a1, V0, V1);                       // hi x lo
        LDM4(c0, arow + A_LO_OFF + ks * 32);
        LDM4(c1, arow + A_LO_OFF + 16 * ROWB + ks * 32);
        mma8(acc, c0, c1, U0, U1);                       // lo x hi
    }
}

#define ZERO_ACC(acc) { \
    _Pragma("unroll") for (int i_ = 0; i_ < 2; ++i_) \
    _Pragma("unroll") for (int j_ = 0; j_ < 4; ++j_) \
    _Pragma("unroll") for (int k_ = 0; k_ < 4; ++k_) (acc)[i_][j_][k_] = 0.f; }

// assemble thread-local float4 covering 4 consecutive logical columns from a
// tile pair (requires the permuted weight packing below)
#define ACC_V4(acc, i, rh, j2) \
    make_float4((acc)[i][2*(j2)][(rh)*2+0], (acc)[i][2*(j2)][(rh)*2+1], \
                (acc)[i][2*(j2)+1][(rh)*2+0], (acc)[i][2*(j2)+1][(rh)*2+1])

// ------------------------- tiny kernels -------------------------------------
__global__ void k_zero(int n_nodes) {
    int i = blockIdx.x * blockDim.x + threadIdx.x;
    int tot4 = n_nodes * (D / 4);
    if (i < tot4) reinterpret_cast<float4*>(g_agg)[i] = make_float4(0.f, 0.f, 0.f, 0.f);
    if (i < n_nodes) g_deg[i] = 0.f;
}

// pack weights in mma-fragment order with column permutation:
// physical col n (0..127): w=n>>5, nt=(n>>3)&3, c=n&7, q=c>>1, r=c&1
// logical  col L = w*32 + 16*(nt>>1) + 4*q + 2*(nt&1) + r
__global__ void k_wprep(const float* __restrict__ We, const float* __restrict__ Wn) {
    int idx = blockIdx.x * blockDim.x + threadIdx.x;
    if (idx >= 5 * 2 * 2048) return;
    int lane = idx & 31, npair = (idx >> 5) & 7, ks = (idx >> 8) & 7;
    int plane = (idx >> 11) & 1, b = idx >> 12;
    const float* W;
    int colbase, ldk;
    if (b < 3) { W = We; ldk = 384; colbase = b * 128; }
    else       { W = Wn; ldk = 256; colbase = (b - 3) * 128; }
    uint32_t out[4];
    #pragma unroll
    for (int j = 0; j < 4; ++j) {
        int n = (npair * 2 + (j >> 1)) * 8 + (lane >> 2);   // physical col
        int w = n >> 5, nt = (n >> 3) & 3, c = n & 7;
        int L = w * 32 + 16 * (nt >> 1) + 4 * (c >> 1) + 2 * (nt & 1) + (c & 1);
        int k = ks * 16 + (lane & 3) * 2 + (j & 1) * 8;
        float w0 = W[(size_t)L * ldk + colbase + k];
        float w1 = W[(size_t)L * ldk + colbase + k + 1];
        __nv_bfloat16 h0 = __float2bfloat16(w0), h1 = __float2bfloat16(w1);
        __nv_bfloat162 v;
        if (plane) {
            v.x = __float2bfloat16(w0 - __bfloat162float(h0));
            v.y = __float2bfloat16(w1 - __bfloat162float(h1));
        } else { v.x = h0; v.y = h1; }
        out[j] = *reinterpret_cast<uint32_t*>(&v);
    }
    g_pk[idx] = make_uint4(out[0], out[1], out[2], out[3]);
}

// ------------------------- main kernels -------------------------------------
// k_pre: persistent, grid (G,2); v4 epilogue
__global__ void __launch_bounds__(256, 3)
k_pre(const float* __restrict__ nf, const float* __restrict__ b_e, int N) {
    extern __shared__ char smem[];
    uint32_t sa = smem_u32(smem);
    int tid = threadIdx.x, lane = tid & 31, warp = tid >> 5;
    int warpm = warp >> 2, warpn = warp & 3;
    int half = blockIdx.y;
    int ntiles = (N + 63) >> 6;
    int q = lane & 3, r4 = lane >> 2;
    int row = tid >> 2, qq = tid & 3;

    int t = blockIdx.x;
    if (t >= ntiles) return;

    float4 P[4];
    {
        bool v = t * 64 + row < N;
        const float4* gr = reinterpret_cast<const float4*>(nf + (size_t)(t * 64 + row) * D + qq * 32);
        #pragma unroll
        for (int j = 0; j < 4; ++j)
            P[j] = v ? __ldg(gr + j) : make_float4(0.f, 0.f, 0.f, 0.f);
    }

    while (t < ntiles) {
        {
            bool v = t * 64 + row < N;
            const float4* gr = reinterpret_cast<const float4*>(nf + (size_t)(t * 64 + row) * D + qq * 32);
            float4 Dq[4];
            #pragma unroll
            for (int j = 0; j < 4; ++j)
                Dq[j] = v ? __ldg(gr + 4 + j) : make_float4(0.f, 0.f, 0.f, 0.f);
            char* ph = smem + row * ROWB + qq * 64;
            cvt_store(ph, P[0], P[1], 0, 1.f);
            cvt_store(ph, P[2], P[3], 1, 1.f);
            cvt_store(ph, Dq[0], Dq[1], 2, 1.f);
            cvt_store(ph, Dq[2], Dq[3], 3, 1.f);
        }
        __syncthreads();
        int tn = t + gridDim.x;
        if (tn < ntiles) {
            bool v = tn * 64 + row < N;
            const float4* gr = reinterpret_cast<const float4*>(nf + (size_t)(tn * 64 + row) * D + qq * 32);
            #pragma unroll
            for (int j = 0; j < 4; ++j)
                P[j] = v ? __ldg(gr + j) : make_float4(0.f, 0.f, 0.f, 0.f);
        }

        float acc[2][4][4];
        ZERO_ACC(acc);
        run_mma(sa, half, warpm, warpn, lane, acc);

        int mbase = t * 64;
        #pragma unroll
        for (int i = 0; i < 2; ++i)
            #pragma unroll
            for (int rh = 0; rh < 2; ++rh) {
                int m = mbase + warpm * 32 + i * 16 + rh * 8 + r4;
                if (m < N) {
                    float* pd = g_AB + (size_t)m * 256 + half * 128;
                    #pragma unroll
                    for (int j2 = 0; j2 < 2; ++j2) {
                        int col4 = warpn * 32 + j2 * 16 + q * 4;
                        float4 V = ACC_V4(acc, i, rh, j2);
                        if (half == 1) {
                            float4 bb = *reinterpret_cast<const float4*>(b_e + col4);
                            V.x += bb.x; V.y += bb.y; V.z += bb.z; V.w += bb.w;
                        }
                        *reinterpret_cast<float4*>(pd + col4) = V;
                    }
                }
            }
        __syncthreads();
        t = tn;
    }
}

// k_edge: persistent; idx preloaded + deg red before MMA; all-v4 epilogue with
// hoistable gathers (non-volatile ldcg4 overlaps them with the MMA tail)
__global__ void __launch_bounds__(256, 3)
k_edge(const float* __restrict__ ef, const int* __restrict__ src,
       const int* __restrict__ dst, float* __restrict__ e_out, int E) {
    extern __shared__ char smem[];
    uint32_t sa = smem_u32(smem);
    int tid = threadIdx.x, lane = tid & 31, warp = tid >> 5;
    int warpm = warp >> 2, warpn = warp & 3;
    int ntiles = E >> 6;
    int q = lane & 3, r4 = lane >> 2;
    int row = tid >> 2, qq = tid & 3;

    int t = blockIdx.x;
    if (t >= ntiles) return;

    float4 P[4];
    {
        const float4* gr = reinterpret_cast<const float4*>(ef + (size_t)(t * 64 + row) * D + qq * 32);
        #pragma unroll
        for (int j = 0; j < 4; ++j) P[j] = __ldcs(gr + j);
    }

    while (t < ntiles) {
        {
            const float4* gr = reinterpret_cast<const float4*>(ef + (size_t)(t * 64 + row) * D + qq * 32);
            float4 Dq[4];
            #pragma unroll
            for (int j = 0; j < 4; ++j) Dq[j] = __ldcs(gr + 4 + j);
            char* ph = smem + row * ROWB + qq * 64;
            cvt_store(ph, P[0], P[1], 0, 1.f);
            cvt_store(ph, P[2], P[3], 1, 1.f);
            cvt_store(ph, Dq[0], Dq[1], 2, 1.f);
            cvt_store(ph, Dq[2], Dq[3], 3, 1.f);
        }
        __syncthreads();
        int tn = t + gridDim.x;
        if (tn < ntiles) {
            const float4* gr = reinterpret_cast<const float4*>(ef + (size_t)(tn * 64 + row) * D + qq * 32);
            #pragma unroll
            for (int j = 0; j < 4; ++j) P[j] = __ldcs(gr + j);
        }

        // preload indices + deg reduction (acc-independent; hides under MMA)
        int mbase = t * 64;
        int sidx[2][2], didx[2][2];
        #pragma unroll
        for (int i = 0; i < 2; ++i)
            #pragma unroll
            for (int rh = 0; rh < 2; ++rh) {
                int m = mbase + warpm * 32 + i * 16 + rh * 8 + r4;
                sidx[i][rh] = __ldg(src + m);
                didx[i][rh] = __ldg(dst + m);
                if (q == 0 && warpn == 0) atomicAdd(&g_deg[didx[i][rh]], 1.0f);
            }

        float acc[2][4][4];
        ZERO_ACC(acc);
        run_mma(sa, 2, warpm, warpn, lane, acc);

        // v4 epilogue: thread-local float4 per tile pair (permuted packing)
        #pragma unroll
        for (int i = 0; i < 2; ++i)
            #pragma unroll
            for (int rh = 0; rh < 2; ++rh) {
                int rl = warpm * 32 + i * 16 + rh * 8 + r4;
                int m = mbase + rl;
                const float* pA = g_AB + (size_t)sidx[i][rh] * 256;
                const float* pB = g_AB + (size_t)didx[i][rh] * 256 + 128;
                float* pe = e_out + (size_t)m * D;
                float* pg = g_agg + (size_t)didx[i][rh] * D;
                #pragma unroll
                for (int j2 = 0; j2 < 2; ++j2) {
                    int col4 = warpn * 32 + j2 * 16 + q * 4;
                    float4 av = ldcg4(pA + col4);
                    float4 bv = ldcg4(pB + col4);
                    float4 V = ACC_V4(acc, i, rh, j2);
                    V.x += av.x + bv.x;
                    V.y += av.y + bv.y;
                    V.z += av.z + bv.z;
                    V.w += av.w + bv.w;
                    __stcs(reinterpret_cast<float4*>(pe + col4), V);
                    red_v4(pg + col4, V);
                }
            }
        __syncthreads();
        t = tn;
    }
}

// k_node: persistent; two K-stages (nf, agg/deg); v4 epilogue
__global__ void __launch_bounds__(256, 3)
k_node(const float* __restrict__ nf, const float* __restrict__ b_n,
       float* __restrict__ n_out, int N) {
    extern __shared__ char smem[];
    uint32_t sa = smem_u32(smem);
    int tid = threadIdx.x, lane = tid & 31, warp = tid >> 5;
    int warpm = warp >> 2, warpn = warp & 3;
    int ntiles = (N + 63) >> 6;
    int q = lane & 3, r4 = lane >> 2;
    int row = tid >> 2, qq = tid & 3;

    for (int t = blockIdx.x; t < ntiles; t += gridDim.x) {
        int mbase = t * 64;
        int nrows = min(64, N - mbase);

        {
            bool v = row < nrows;
            const float4* gr = reinterpret_cast<const float4*>(nf + (size_t)(mbase + row) * D + qq * 32);
            char* ph = smem + row * ROWB + qq * 64;
            #pragma unroll
            for (int jj = 0; jj < 4; ++jj) {
                float4 f0 = v ? __ldg(gr + 2 * jj)     : make_float4(0.f, 0.f, 0.f, 0.f);
                float4 f1 = v ? __ldg(gr + 2 * jj + 1) : make_float4(0.f, 0.f, 0.f, 0.f);
                cvt_store(ph, f0, f1, jj, 1.f);
            }
        }
        __syncthreads();

        float acc[2][4][4];
        ZERO_ACC(acc);
        run_mma(sa, 3, warpm, warpn, lane, acc);
        __syncthreads();

        {
            bool v = row < nrows;
            float s = v ? 1.f / fmaxf(__ldg(g_deg + mbase + row), 1.f) : 1.f;
            const float4* gr = reinterpret_cast<const float4*>(g_agg + (size_t)(mbase + row) * D + qq * 32);
            char* ph = smem + row * ROWB + qq * 64;
            #pragma unroll
            for (int jj = 0; jj < 4; ++jj) {
                float4 f0 = v ? __ldg(gr + 2 * jj)     : make_float4(0.f, 0.f, 0.f, 0.f);
                float4 f1 = v ? __ldg(gr + 2 * jj + 1) : make_float4(0.f, 0.f, 0.f, 0.f);
                cvt_store(ph, f0, f1, jj, s);
            }
        }
        __syncthreads();
        run_mma(sa, 4, warpm, warpn, lane, acc);

        #pragma unroll
        for (int i = 0; i < 2; ++i)
            #pragma unroll
            for (int rh = 0; rh < 2; ++rh) {
                int m = mbase + warpm * 32 + i * 16 + rh * 8 + r4;
                if (m < N) {
                    float* pd = n_out + (size_t)m * D;
                    #pragma unroll
                    for (int j2 = 0; j2 < 2; ++j2) {
                        int col4 = warpn * 32 + j2 * 16 + q * 4;
                        float4 V = ACC_V4(acc, i, rh, j2);
                        float4 bb = *reinterpret_cast<const float4*>(b_n + col4);
                        V.x += bb.x; V.y += bb.y; V.z += bb.z; V.w += bb.w;
                        *reinterpret_cast<float4*>(pd + col4) = V;
                    }
                }
            }
        __syncthreads();
    }
}

// ---------------------------------------------------------------------------
extern "C" void kernel_launch(void* const* d_in, const int* in_sizes, int n_in,
                              void* d_out, int out_size) {
    const float* nf  = (const float*)d_in[0];
    const float* ef  = (const float*)d_in[1];
    const int*   src = (const int*)d_in[2];   // int32 (JAX x64 disabled)
    const int*   dst = (const int*)d_in[3];
    const float* We  = (const float*)d_in[4];
    const float* be  = (const float*)d_in[5];
    const float* Wn  = (const float*)d_in[6];
    const float* bn  = (const float*)d_in[7];

    int N = in_sizes[0] / D;
    int E = in_sizes[1] / D;

    float* n_out = (float*)d_out;
    float* e_out = n_out + (size_t)N * D;

    cudaFuncSetAttribute(k_pre,  cudaFuncAttributeMaxDynamicSharedMemorySize, SMEM_TILE);
    cudaFuncSetAttribute(k_edge, cudaFuncAttributeMaxDynamicSharedMemorySize, SMEM_TILE);
    cudaFuncSetAttribute(k_node, cudaFuncAttributeMaxDynamicSharedMemorySize, SMEM_TILE);

    int zthreads = N * (D / 4);
    k_zero<<<(zthreads + 255) / 256, 256>>>(N);
    k_wprep<<<(5 * 2 * 2048 + 255) / 256, 256>>>(We, Wn);

    dim3 gpre(444, 2);
    k_pre<<<gpre, 256, SMEM_TILE>>>(nf, be, N);
    k_edge<<<444, 256, SMEM_TILE>>>(ef, src, dst, e_out, E);
    k_node<<<444, 256, SMEM_TILE>>>(nf, bn, n_out, N);
}

// round 16
// speedup vs baseline: 1.0487x; 1.0487x over previous
#include <cuda_runtime.h>
#include <cuda_bf16.h>
#include <cstdint>

#define D 128
#define MAXN 40000

// ------------------------- device scratch (no allocs) -----------------------
__device__ __align__(16) float g_AB[(size_t)MAXN * 256]; // [N][256]: A=nf@W1^T | B'=nf@W2^T+b_e
__device__ __align__(16) float g_agg[(size_t)MAXN * D];
__device__ __align__(16) float g_deg[MAXN];
// Fragment-packed weights, COLUMN-PERMUTED so each thread's acc covers 4
// consecutive logical columns per tile-pair (enables v4 epilogue ops).
__device__ __align__(16) uint4 g_pk[5 * 2 * 2048];

// ------------------------- smem layout --------------------------------------
#define ROWB 272                  // 136 bf16/row: 4-bank shift/row, LDSM conflict-free
#define A_LO_OFF 17408            // 64*272
#define SMEM_TILE 34816
#define STG_STRIDE 132            // stage row stride in floats (overlays A tile)

__device__ __forceinline__ uint32_t smem_u32(const void* p) {
    uint32_t a;
    asm("{ .reg .u64 t; cvta.to.shared.u64 t, %1; cvt.u32.u64 %0, t; }" : "=r"(a) : "l"(p));
    return a;
}

#define LDM4(r, addr) \
    asm volatile("ldmatrix.sync.aligned.m8n8.x4.shared.b16 {%0,%1,%2,%3}, [%4];" \
        : "=r"((r)[0]), "=r"((r)[1]), "=r"((r)[2]), "=r"((r)[3]) : "r"(addr))

__device__ __forceinline__ void mma16816(float* c, const uint32_t* a, uint32_t b0, uint32_t b1) {
    asm volatile("mma.sync.aligned.m16n8k16.row.col.f32.bf16.bf16.f32 "
        "{%0,%1,%2,%3}, {%4,%5,%6,%7}, {%8,%9}, {%0,%1,%2,%3};"
        : "+f"(c[0]), "+f"(c[1]), "+f"(c[2]), "+f"(c[3])
        : "r"(a[0]), "r"(a[1]), "r"(a[2]), "r"(a[3]), "r"(b0), "r"(b1));
}

// no "memory" clobber: lets the compiler batch independent gathers around reds
__device__ __forceinline__ void red_v4(float* p, float4 v) {
    asm volatile("red.global.add.v4.f32 [%0], {%1,%2,%3,%4};"
                 :: "l"(p), "f"(v.x), "f"(v.y), "f"(v.z), "f"(v.w));
}

// NOT volatile: pure load; allows scheduling into the surrounding latency shadow
__device__ __forceinline__ float4 ldcg4(const float* p) {
    float4 v;
    asm("ld.global.cg.v4.f32 {%0,%1,%2,%3}, [%4];"
        : "=f"(v.x), "=f"(v.y), "=f"(v.z), "=f"(v.w) : "l"(p));
    return v;
}

__device__ __forceinline__ void split2(float x, float y, uint32_t& h, uint32_t& l) {
    __nv_bfloat162 hh = __floats2bfloat162_rn(x, y);
    __nv_bfloat162 ll = __floats2bfloat162_rn(x - __bfloat162float(hh.x),
                                              y - __bfloat162float(hh.y));
    h = *reinterpret_cast<uint32_t*>(&hh);
    l = *reinterpret_cast<uint32_t*>(&ll);
}

__device__ __forceinline__ void cvt_store(char* ph, float4 f0, float4 f1, int jj, float s) {
    f0.x *= s; f0.y *= s; f0.z *= s; f0.w *= s;
    f1.x *= s; f1.y *= s; f1.z *= s; f1.w *= s;
    uint4 H, L;
    split2(f0.x, f0.y, H.x, L.x);
    split2(f0.z, f0.w, H.y, L.y);
    split2(f1.x, f1.y, H.z, L.z);
    split2(f1.z, f1.w, H.w, L.w);
    *reinterpret_cast<uint4*>(ph + jj * 16) = H;
    *reinterpret_cast<uint4*>(ph + A_LO_OFF + jj * 16) = L;
}

// ---- 8-mma block helper -----------------------------------------------------
__device__ __forceinline__ void mma8(float acc[2][4][4], const uint32_t* a0,
                                     const uint32_t* a1, uint4 U0, uint4 U1) {
    mma16816(acc[0][0], a0, U0.x, U0.y);
    mma16816(acc[0][1], a0, U0.z, U0.w);
    mma16816(acc[0][2], a0, U1.x, U1.y);
    mma16816(acc[0][3], a0, U1.z, U1.w);
    mma16816(acc[1][0], a1, U0.x, U0.y);
    mma16816(acc[1][1], a1, U0.z, U0.w);
    mma16816(acc[1][2], a1, U1.x, U1.y);
    mma16816(acc[1][3], a1, U1.z, U1.w);
}

// 3-pass 64x128x128 MMA; B hi+lo via __ldg (L1), A via LDSM, a_hi reused
__device__ __forceinline__ void run_mma(uint32_t sa, int block, int warpm, int warpn,
                                        int lane, float acc[2][4][4]) {
    uint32_t arow = sa + (warpm * 32 + (lane & 15)) * ROWB + (lane >> 4) * 16;
    const uint4* __restrict__ Bb = g_pk + (size_t)block * 2 * 2048;
    int boff = warpn * 64 + lane;
    #pragma unroll
    for (int ks = 0; ks < 8; ++ks) {
        uint32_t a0[4], a1[4], c0[4], c1[4];
        uint4 U0 = __ldg(Bb + ks * 256 + boff);
        uint4 U1 = __ldg(Bb + ks * 256 + boff + 32);
        uint4 V0 = __ldg(Bb + 2048 + ks * 256 + boff);
        uint4 V1 = __ldg(Bb + 2048 + ks * 256 + boff + 32);
        LDM4(a0, arow + ks * 32);
        LDM4(a1, arow + 16 * ROWB + ks * 32);
        mma8(acc, a0, a1, U0, U1);                       // hi x hi
        mma8(acc, a0, a1, V0, V1);                       // hi x lo
        LDM4(c0, arow + A_LO_OFF + ks * 32);
        LDM4(c1, arow + A_LO_OFF + 16 * ROWB + ks * 32);
        mma8(acc, c0, c1, U0, U1);                       // lo x hi
    }
}

#define ZERO_ACC(acc) { \
    _Pragma("unroll") for (int i_ = 0; i_ < 2; ++i_) \
    _Pragma("unroll") for (int j_ = 0; j_ < 4; ++j_) \
    _Pragma("unroll") for (int k_ = 0; k_ < 4; ++k_) (acc)[i_][j_][k_] = 0.f; }

// assemble thread-local float4 covering 4 consecutive logical columns from a
// tile pair (requires the permuted weight packing below)
#define ACC_V4(acc, i, rh, j2) \
    make_float4((acc)[i][2*(j2)][(rh)*2+0], (acc)[i][2*(j2)][(rh)*2+1], \
                (acc)[i][2*(j2)+1][(rh)*2+0], (acc)[i][2*(j2)+1][(rh)*2+1])

// ------------------------- tiny kernels -------------------------------------
__global__ void k_zero(int n_nodes) {
    int i = blockIdx.x * blockDim.x + threadIdx.x;
    int tot4 = n_nodes * (D / 4);
    if (i < tot4) reinterpret_cast<float4*>(g_agg)[i] = make_float4(0.f, 0.f, 0.f, 0.f);
    if (i < n_nodes) g_deg[i] = 0.f;
}

// pack weights in mma-fragment order with column permutation:
// physical col n (0..127): w=n>>5, nt=(n>>3)&3, c=n&7, q=c>>1, r=c&1
// logical  col L = w*32 + 16*(nt>>1) + 4*q + 2*(nt&1) + r
__global__ void k_wprep(const float* __restrict__ We, const float* __restrict__ Wn) {
    int idx = blockIdx.x * blockDim.x + threadIdx.x;
    if (idx >= 5 * 2 * 2048) return;
    int lane = idx & 31, npair = (idx >> 5) & 7, ks = (idx >> 8) & 7;
    int plane = (idx >> 11) & 1, b = idx >> 12;
    const float* W;
    int colbase, ldk;
    if (b < 3) { W = We; ldk = 384; colbase = b * 128; }
    else       { W = Wn; ldk = 256; colbase = (b - 3) * 128; }
    uint32_t out[4];
    #pragma unroll
    for (int j = 0; j < 4; ++j) {
        int n = (npair * 2 + (j >> 1)) * 8 + (lane >> 2);   // physical col
        int w = n >> 5, nt = (n >> 3) & 3, c = n & 7;
        int L = w * 32 + 16 * (nt >> 1) + 4 * (c >> 1) + 2 * (nt & 1) + (c & 1);
        int k = ks * 16 + (lane & 3) * 2 + (j & 1) * 8;
        float w0 = W[(size_t)L * ldk + colbase + k];
        float w1 = W[(size_t)L * ldk + colbase + k + 1];
        __nv_bfloat16 h0 = __float2bfloat16(w0), h1 = __float2bfloat16(w1);
        __nv_bfloat162 v;
        if (plane) {
            v.x = __float2bfloat16(w0 - __bfloat162float(h0));
            v.y = __float2bfloat16(w1 - __bfloat162float(h1));
        } else { v.x = h0; v.y = h1; }
        out[j] = *reinterpret_cast<uint32_t*>(&v);
    }
    g_pk[idx] = make_uint4(out[0], out[1], out[2], out[3]);
}

// ------------------------- main kernels -------------------------------------
// k_pre: persistent, grid (G,2); v4 epilogue
__global__ void __launch_bounds__(256, 3)
k_pre(const float* __restrict__ nf, const float* __restrict__ b_e, int N) {
    extern __shared__ char smem[];
    uint32_t sa = smem_u32(smem);
    int tid = threadIdx.x, lane = tid & 31, warp = tid >> 5;
    int warpm = warp >> 2, warpn = warp & 3;
    int half = blockIdx.y;
    int ntiles = (N + 63) >> 6;
    int q = lane & 3, r4 = lane >> 2;
    int row = tid >> 2, qq = tid & 3;

    int t = blockIdx.x;
    if (t >= ntiles) return;

    float4 P[4];
    {
        bool v = t * 64 + row < N;
        const float4* gr = reinterpret_cast<const float4*>(nf + (size_t)(t * 64 + row) * D + qq * 32);
        #pragma unroll
        for (int j = 0; j < 4; ++j)
            P[j] = v ? __ldg(gr + j) : make_float4(0.f, 0.f, 0.f, 0.f);
    }

    while (t < ntiles) {
        {
            bool v = t * 64 + row < N;
            const float4* gr = reinterpret_cast<const float4*>(nf + (size_t)(t * 64 + row) * D + qq * 32);
            float4 Dq[4];
            #pragma unroll
            for (int j = 0; j < 4; ++j)
                Dq[j] = v ? __ldg(gr + 4 + j) : make_float4(0.f, 0.f, 0.f, 0.f);
            char* ph = smem + row * ROWB + qq * 64;
            cvt_store(ph, P[0], P[1], 0, 1.f);
            cvt_store(ph, P[2], P[3], 1, 1.f);
            cvt_store(ph, Dq[0], Dq[1], 2, 1.f);
            cvt_store(ph, Dq[2], Dq[3], 3, 1.f);
        }
        __syncthreads();
        int tn = t + gridDim.x;
        if (tn < ntiles) {
            bool v = tn * 64 + row < N;
            const float4* gr = reinterpret_cast<const float4*>(nf + (size_t)(tn * 64 + row) * D + qq * 32);
            #pragma unroll
            for (int j = 0; j < 4; ++j)
                P[j] = v ? __ldg(gr + j) : make_float4(0.f, 0.f, 0.f, 0.f);
        }

        float acc[2][4][4];
        ZERO_ACC(acc);
        run_mma(sa, half, warpm, warpn, lane, acc);

        int mbase = t * 64;
        #pragma unroll
        for (int i = 0; i < 2; ++i)
            #pragma unroll
            for (int rh = 0; rh < 2; ++rh) {
                int m = mbase + warpm * 32 + i * 16 + rh * 8 + r4;
                if (m < N) {
                    float* pd = g_AB + (size_t)m * 256 + half * 128;
                    #pragma unroll
                    for (int j2 = 0; j2 < 2; ++j2) {
                        int col4 = warpn * 32 + j2 * 16 + q * 4;
                        float4 V = ACC_V4(acc, i, rh, j2);
                        if (half == 1) {
                            float4 bb = *reinterpret_cast<const float4*>(b_e + col4);
                            V.x += bb.x; V.y += bb.y; V.z += bb.z; V.w += bb.w;
                        }
                        *reinterpret_cast<float4*>(pd + col4) = V;
                    }
                }
            }
        __syncthreads();
        t = tn;
    }
}

// k_edge: persistent; staged row-coalesced epilogue overlaying A smem.
// After the MMA, acc is staged to smem in logical column order; each warp then
// owns 8 full edge rows: full-row gathers (4 wf), coalesced store and red.v4.
__global__ void __launch_bounds__(256, 3)
k_edge(const float* __restrict__ ef, const int* __restrict__ src,
       const int* __restrict__ dst, float* __restrict__ e_out, int E) {
    extern __shared__ char smem[];
    uint32_t sa = smem_u32(smem);
    float* stage = reinterpret_cast<float*>(smem);   // overlays A tile (free post-MMA)
    int tid = threadIdx.x, lane = tid & 31, warp = tid >> 5;
    int warpm = warp >> 2, warpn = warp & 3;
    int ntiles = E >> 6;
    int q = lane & 3, r4 = lane >> 2;
    int row = tid >> 2, qq = tid & 3;

    int t = blockIdx.x;
    if (t >= ntiles) return;

    float4 P[4];
    {
        const float4* gr = reinterpret_cast<const float4*>(ef + (size_t)(t * 64 + row) * D + qq * 32);
        #pragma unroll
        for (int j = 0; j < 4; ++j) P[j] = __ldcs(gr + j);
    }

    while (t < ntiles) {
        {
            const float4* gr = reinterpret_cast<const float4*>(ef + (size_t)(t * 64 + row) * D + qq * 32);
            float4 Dq[4];
            #pragma unroll
            for (int j = 0; j < 4; ++j) Dq[j] = __ldcs(gr + 4 + j);
            char* ph = smem + row * ROWB + qq * 64;
            cvt_store(ph, P[0], P[1], 0, 1.f);
            cvt_store(ph, P[2], P[3], 1, 1.f);
            cvt_store(ph, Dq[0], Dq[1], 2, 1.f);
            cvt_store(ph, Dq[2], Dq[3], 3, 1.f);
        }
        __syncthreads();
        int tn = t + gridDim.x;
        if (tn < ntiles) {
            const float4* gr = reinterpret_cast<const float4*>(ef + (size_t)(tn * 64 + row) * D + qq * 32);
            #pragma unroll
            for (int j = 0; j < 4; ++j) P[j] = __ldcs(gr + j);
        }

        // deg reduction (acc-independent; hides under MMA)
        int mbase = t * 64;
        if (warpn == 0 && q == 0) {
            #pragma unroll
            for (int i = 0; i < 2; ++i)
                #pragma unroll
                for (int rh = 0; rh < 2; ++rh) {
                    int m = mbase + warpm * 32 + i * 16 + rh * 8 + r4;
                    atomicAdd(&g_deg[__ldg(dst + m)], 1.0f);
                }
        }

        float acc[2][4][4];
        ZERO_ACC(acc);
        run_mma(sa, 2, warpm, warpn, lane, acc);
        __syncthreads();                       // all warps done reading A smem

        // stage acc -> smem in plain logical column order
        #pragma unroll
        for (int i = 0; i < 2; ++i)
            #pragma unroll
            for (int rh = 0; rh < 2; ++rh) {
                int rl = warpm * 32 + i * 16 + rh * 8 + r4;
                #pragma unroll
                for (int j2 = 0; j2 < 2; ++j2) {
                    int col4 = warpn * 32 + j2 * 16 + q * 4;
                    *reinterpret_cast<float4*>(stage + rl * STG_STRIDE + col4) =
                        ACC_V4(acc, i, rh, j2);
                }
            }
        __syncthreads();

        // row-coalesced combine: warp w owns rows w*8 .. w*8+7
        #pragma unroll
        for (int r = 0; r < 8; ++r) {
            int rl = warp * 8 + r;
            int m = mbase + rl;
            int s = __ldg(src + m), d2 = __ldg(dst + m);
            float4 st = *reinterpret_cast<const float4*>(stage + rl * STG_STRIDE + lane * 4);
            float4 a = ldcg4(g_AB + (size_t)s * 256 + lane * 4);
            float4 b = ldcg4(g_AB + (size_t)d2 * 256 + 128 + lane * 4);
            float4 V = make_float4(st.x + a.x + b.x, st.y + a.y + b.y,
                                   st.z + a.z + b.z, st.w + a.w + b.w);
            __stcs(reinterpret_cast<float4*>(e_out + (size_t)m * D) + lane, V);
            red_v4(g_agg + (size_t)d2 * D + lane * 4, V);
        }
        __syncthreads();
        t = tn;
    }
}

// k_node: persistent; two K-stages (nf, agg/deg); v4 epilogue
__global__ void __launch_bounds__(256, 3)
k_node(const float* __restrict__ nf, const float* __restrict__ b_n,
       float* __restrict__ n_out, int N) {
    extern __shared__ char smem[];
    uint32_t sa = smem_u32(smem);
    int tid = threadIdx.x, lane = tid & 31, warp = tid >> 5;
    int warpm = warp >> 2, warpn = warp & 3;
    int ntiles = (N + 63) >> 6;
    int q = lane & 3, r4 = lane >> 2;
    int row = tid >> 2, qq = tid & 3;

    for (int t = blockIdx.x; t < ntiles; t += gridDim.x) {
        int mbase = t * 64;
        int nrows = min(64, N - mbase);

        {
            bool v = row < nrows;
            const float4* gr = reinterpret_cast<const float4*>(nf + (size_t)(mbase + row) * D + qq * 32);
            char* ph = smem + row * ROWB + qq * 64;
            #pragma unroll
            for (int jj = 0; jj < 4; ++jj) {
                float4 f0 = v ? __ldg(gr + 2 * jj)     : make_float4(0.f, 0.f, 0.f, 0.f);
                float4 f1 = v ? __ldg(gr + 2 * jj + 1) : make_float4(0.f, 0.f, 0.f, 0.f);
                cvt_store(ph, f0, f1, jj, 1.f);
            }
        }
        __syncthreads();

        float acc[2][4][4];
        ZERO_ACC(acc);
        run_mma(sa, 3, warpm, warpn, lane, acc);
        __syncthreads();

        {
            bool v = row < nrows;
            float s = v ? 1.f / fmaxf(__ldg(g_deg + mbase + row), 1.f) : 1.f;
            const float4* gr = reinterpret_cast<const float4*>(g_agg + (size_t)(mbase + row) * D + qq * 32);
            char* ph = smem + row * ROWB + qq * 64;
            #pragma unroll
            for (int jj = 0; jj < 4; ++jj) {
                float4 f0 = v ? __ldg(gr + 2 * jj)     : make_float4(0.f, 0.f, 0.f, 0.f);
                float4 f1 = v ? __ldg(gr + 2 * jj + 1) : make_float4(0.f, 0.f, 0.f, 0.f);
                cvt_store(ph, f0, f1, jj, s);
            }
        }
        __syncthreads();
        run_mma(sa, 4, warpm, warpn, lane, acc);

        #pragma unroll
        for (int i = 0; i < 2; ++i)
            #pragma unroll
            for (int rh = 0; rh < 2; ++rh) {
                int m = mbase + warpm * 32 + i * 16 + rh * 8 + r4;
                if (m < N) {
                    float* pd = n_out + (size_t)m * D;
                    #pragma unroll
                    for (int j2 = 0; j2 < 2; ++j2) {
                        int col4 = warpn * 32 + j2 * 16 + q * 4;
                        float4 V = ACC_V4(acc, i, rh, j2);
                        float4 bb = *reinterpret_cast<const float4*>(b_n + col4);
                        V.x += bb.x; V.y += bb.y; V.z += bb.z; V.w += bb.w;
                        *reinterpret_cast<float4*>(pd + col4) = V;
                    }
                }
            }
        __syncthreads();
    }
}

// ---------------------------------------------------------------------------
extern "C" void kernel_launch(void* const* d_in, const int* in_sizes, int n_in,
                              void* d_out, int out_size) {
    const float* nf  = (const float*)d_in[0];
    const float* ef  = (const float*)d_in[1];
    const int*   src = (const int*)d_in[2];   // int32 (JAX x64 disabled)
    const int*   dst = (const int*)d_in[3];
    const float* We  = (const float*)d_in[4];
    const float* be  = (const float*)d_in[5];
    const float* Wn  = (const float*)d_in[6];
    const float* bn  = (const float*)d_in[7];

    int N = in_sizes[0] / D;
    int E = in_sizes[1] / D;

    float* n_out = (float*)d_out;
    float* e_out = n_out + (size_t)N * D;

    cudaFuncSetAttribute(k_pre,  cudaFuncAttributeMaxDynamicSharedMemorySize, SMEM_TILE);
    cudaFuncSetAttribute(k_edge, cudaFuncAttributeMaxDynamicSharedMemorySize, SMEM_TILE);
    cudaFuncSetAttribute(k_node, cudaFuncAttributeMaxDynamicSharedMemorySize, SMEM_TILE);

    int zthreads = N * (D / 4);
    k_zero<<<(zthreads + 255) / 256, 256>>>(N);
    k_wprep<<<(5 * 2 * 2048 + 255) / 256, 256>>>(We, Wn);

    dim3 gpre(444, 2);
    k_pre<<<gpre, 256, SMEM_TILE>>>(nf, be, N);
    k_edge<<<444, 256, SMEM_TILE>>>(ef, src, dst, e_out, E);
    k_node<<<444, 256, SMEM_TILE>>>(nf, bn, n_out, N);
}